// round 17
// baseline (speedup 1.0000x reference)
#include <cuda_runtime.h>
#include <cuda_bf16.h>
#include <cstdint>

// PackedViterbi as a parallel matrix-product tree.
// R17: passA (R16, chunk=16, measured 63.8us) unchanged. passB+passC replaced
// by ONE matvec kernel passV: final answer is 1^T M_0 M_1 ... M_{n-1} 1, so
// after passA only a VECTOR is needed -- chained w^T <- w^T M_k (4k MACs, 8KB
// read per step) replaces full 64x64 GEMMs (262k MACs each). 1 CTA per seq,
// double-buffered tile copy, fp32 compute, exact power-of-2 rescale per step.

static constexpr int S   = 64;
static constexpr int TT  = 512;
static constexpr int BB  = 64;
static constexpr int CH  = 16;            // leaves per passA chunk
static constexpr int NC  = TT / CH;       // 32 chunks per sequence
static constexpr int LDA = 72;
static constexpr int TILE = S * LDA;

__device__ __nv_bfloat16 g_buf1[NC * BB * S * S];
__device__ float         g_off1[NC * BB];

__device__ __forceinline__ float ex2f_(float x) {
    float y; asm("ex2.approx.ftz.f32 %0, %1;" : "=f"(y) : "f"(x)); return y;
}
__device__ __forceinline__ uint32_t bf2u(__nv_bfloat162 v) { return *reinterpret_cast<uint32_t*>(&v); }
__device__ __forceinline__ void mma16816(float c[4], const uint32_t a[4],
                                         uint32_t b0, uint32_t b1) {
    asm volatile(
        "mma.sync.aligned.m16n8k16.row.col.f32.bf16.bf16.f32 "
        "{%0,%1,%2,%3}, {%4,%5,%6,%7}, {%8,%9}, {%0,%1,%2,%3};\n"
        : "+f"(c[0]), "+f"(c[1]), "+f"(c[2]), "+f"(c[3])
        : "r"(a[0]), "r"(a[1]), "r"(a[2]), "r"(a[3]), "r"(b0), "r"(b1));
}
__device__ __forceinline__ void ldm_x4_t(uint32_t a[4], uint32_t addr) {
    asm volatile("ldmatrix.sync.aligned.m8n8.x4.trans.shared.b16 {%0,%1,%2,%3}, [%4];"
                 : "=r"(a[0]), "=r"(a[1]), "=r"(a[2]), "=r"(a[3]) : "r"(addr));
}

struct F8 { float4 a, b; };
__device__ __forceinline__ F8 ldg8(const float* __restrict__ p) {
    F8 r; const float4* q = (const float4*)p; r.a = q[0]; r.b = q[1]; return r;
}
__device__ __forceinline__ void conv_store(const F8& v, __nv_bfloat16* s) {
    const float L2E = 1.4426950408889634f;
    int idx = threadIdx.x * 8;
    float e[8];
    e[0] = ex2f_(fmaf(v.a.x, L2E, -16.f)); e[1] = ex2f_(fmaf(v.a.y, L2E, -16.f));
    e[2] = ex2f_(fmaf(v.a.z, L2E, -16.f)); e[3] = ex2f_(fmaf(v.a.w, L2E, -16.f));
    e[4] = ex2f_(fmaf(v.b.x, L2E, -16.f)); e[5] = ex2f_(fmaf(v.b.y, L2E, -16.f));
    e[6] = ex2f_(fmaf(v.b.z, L2E, -16.f)); e[7] = ex2f_(fmaf(v.b.w, L2E, -16.f));
    __nv_bfloat16 t[8];
#pragma unroll
    for (int q = 0; q < 8; ++q) t[q] = __float2bfloat16(e[q]);
    *(uint4*)(s + (idx >> 6) * LDA + (idx & 63)) = *(uint4*)t;
}

template <bool ATRANS>
__device__ __forceinline__ void cta_compute(const __nv_bfloat16* Asm,
                                            const __nv_bfloat16* Btsm,
                                            float c[2][4]) {
    const int tid = threadIdx.x;
    const int w = tid >> 5, lane = tid & 31;
    const int g = lane >> 2, t4 = lane & 3;
    const int rb = (w >> 2) * 16;
    const int ng = (w & 3) * 2;

    uint32_t a[4][4];
    if (ATRANS) {
        const int mi = lane >> 3, r8 = lane & 7;
        const int colA = rb + ((mi & 1) ? 8 : 0);
        const int rowO = ((mi & 2) ? 8 : 0) + r8;
#pragma unroll
        for (int ks = 0; ks < 4; ++ks) {
            uint32_t ad = (uint32_t)__cvta_generic_to_shared(
                Asm + (ks * 16 + rowO) * LDA + colA);
            ldm_x4_t(a[ks], ad);
        }
    } else {
#pragma unroll
        for (int ks = 0; ks < 4; ++ks) {
            const __nv_bfloat16* base = Asm + (rb + g) * LDA + ks * 16 + t4 * 2;
            a[ks][0] = *(const uint32_t*)(base);
            a[ks][1] = *(const uint32_t*)(base + 8 * LDA);
            a[ks][2] = *(const uint32_t*)(base + 8);
            a[ks][3] = *(const uint32_t*)(base + 8 * LDA + 8);
        }
    }
#pragma unroll
    for (int nt = 0; nt < 2; ++nt) {
        c[nt][0] = c[nt][1] = c[nt][2] = c[nt][3] = 0.f;
        const int n0 = (ng + nt) * 8;
#pragma unroll
        for (int ks = 0; ks < 4; ++ks) {
            const __nv_bfloat16* bb = Btsm + (n0 + g) * LDA + ks * 16 + t4 * 2;
            uint32_t b0 = *(const uint32_t*)bb;
            uint32_t b1 = *(const uint32_t*)(bb + 8);
            mma16816(c[nt], a[ks], b0, b1);
        }
    }
}

__device__ __forceinline__ void wb_smem(const float c[2][4], float scl,
                                        __nv_bfloat16* dst) {
    const int tid = threadIdx.x;
    const int w = tid >> 5, lane = tid & 31;
    const int g = lane >> 2, t4 = lane & 3;
    const int rb = (w >> 2) * 16;
    const int ng = (w & 3) * 2;
#pragma unroll
    for (int nt = 0; nt < 2; ++nt) {
        int col = (ng + nt) * 8 + t4 * 2;
        *(uint32_t*)(dst + (rb + g) * LDA + col)     = bf2u(__floats2bfloat162_rn(c[nt][0] * scl, c[nt][1] * scl));
        *(uint32_t*)(dst + (rb + g + 8) * LDA + col) = bf2u(__floats2bfloat162_rn(c[nt][2] * scl, c[nt][3] * scl));
    }
}
__device__ __forceinline__ void wb_global(const float c[2][4], float scl,
                                          __nv_bfloat16* __restrict__ dst) {
    const int tid = threadIdx.x;
    const int w = tid >> 5, lane = tid & 31;
    const int g = lane >> 2, t4 = lane & 3;
    const int rb = (w >> 2) * 16;
    const int ng = (w & 3) * 2;
#pragma unroll
    for (int nt = 0; nt < 2; ++nt) {
        int col = (ng + nt) * 8 + t4 * 2;
        *(uint32_t*)(dst + (rb + g) * S + col)     = bf2u(__floats2bfloat162_rn(c[nt][0] * scl, c[nt][1] * scl));
        *(uint32_t*)(dst + (rb + g + 8) * S + col) = bf2u(__floats2bfloat162_rn(c[nt][2] * scl, c[nt][3] * scl));
    }
}

__device__ __forceinline__ void exact_scale(const float c[2][4], float* red,
                                            float& scale, float& sft) {
    const int tid = threadIdx.x;
    const int w = tid >> 5, lane = tid & 31;
    float m = 0.f;
#pragma unroll
    for (int nt = 0; nt < 2; ++nt)
#pragma unroll
        for (int q = 0; q < 4; ++q) m = fmaxf(m, c[nt][q]);
#pragma unroll
    for (int o = 16; o; o >>= 1)
        m = fmaxf(m, __shfl_xor_sync(0xffffffffu, m, o));
    if (lane == 0) red[w] = m;
    __syncthreads();
    if (tid == 0) {
        float mm = red[0];
#pragma unroll
        for (int i = 1; i < 16; ++i) mm = fmaxf(mm, red[i]);
        int s = (int)((__float_as_uint(mm) >> 23) & 0xFF) - 126;
        red[16] = __uint_as_float((uint32_t)(127 - s) << 23);
        red[17] = (float)s;
    }
    __syncthreads();
    scale = red[16];
    sft   = red[17];
}

// ---- Pass A (R16: chunk = 16 leaves) ------------------------------------------
__global__ void __launch_bounds__(512, 2)
passA(const float* __restrict__ theta, const int* __restrict__ lengths) {
    __shared__ __nv_bfloat16 Abuf[2][TILE];
    __shared__ __nv_bfloat16 Bbuf[2][TILE];
    __shared__ float red[20];
    const int c = blockIdx.x, b = blockIdx.y;
    const int L = lengths[b];
    const int t0 = c * CH;
    if (L <= t0) return;
    const int thi = min(L, t0 + CH);
    const int idx = threadIdx.x * 8;
    const size_t mat = (size_t)S * S;
    const float* tbase = theta + (size_t)b * mat + idx;
    const size_t tstride = (size_t)BB * mat;

    F8 rA = ldg8(tbase + (size_t)t0 * tstride);

    if (thi == t0 + 1) {                   // single leaf: M = E^T
        conv_store(rA, Abuf[0]);
        __syncthreads();
        const int r = idx >> 6, c0 = idx & 63;
        __nv_bfloat16 t[8];
#pragma unroll
        for (int q = 0; q < 8; ++q) t[q] = Abuf[0][(c0 + q) * LDA + r];
        *(uint4*)(g_buf1 + ((size_t)c * BB + b) * mat + idx) = *(uint4*)t;
        if (threadIdx.x == 0) g_off1[c * BB + b] = 16.f;
        return;
    }

    F8 rN = ldg8(tbase + (size_t)(t0 + 1) * tstride);
    conv_store(rA, Abuf[0]);
    conv_store(rN, Bbuf[0]);
    if (t0 + 2 < thi) rN = ldg8(tbase + (size_t)(t0 + 2) * tstride);
    __syncthreads();

    float c_[2][4];
    cta_compute<true>(Abuf[0], Bbuf[0], c_);          // GEMM 0 (A = E^T)

    const int ngemm = thi - t0 - 1;
    int pa = 0, pb = 0;
    for (int k = 1; k < ngemm; ++k) {
        conv_store(rN, Bbuf[pb ^ 1]);
        if (t0 + k + 2 < thi) rN = ldg8(tbase + (size_t)(t0 + k + 2) * tstride);
        wb_smem(c_, 512.f, Abuf[pa ^ 1]);             // fixed x2^9
        pa ^= 1; pb ^= 1;
        __syncthreads();
        cta_compute<false>(Abuf[pa], Bbuf[pb], c_);
    }

    float scale, sft;
    exact_scale(c_, red, scale, sft);
    wb_global(c_, scale, g_buf1 + ((size_t)c * BB + b) * mat);
    if (threadIdx.x == 0)
        g_off1[c * BB + b] = 16.f * (float)(thi - t0) - 9.f * (float)(ngemm - 1) + sft;
}

// ---- Pass V: chained matvec w^T <- w^T M_k over ascending chunks --------------
// out[b] = ln2 * (log2(sum_j w[j]) + A), A = sum of chunk offsets + step shifts.
__global__ void __launch_bounds__(256, 1)
passV(const int* __restrict__ lengths, float* __restrict__ out) {
    __shared__ __nv_bfloat16 Mt[2][S * S];   // double-buffered chunk tile (8KB each)
    __shared__ float wbuf[S];
    __shared__ float red[4];
    const int b = blockIdx.x;
    const int n = (lengths[b] + CH - 1) / CH;   // #chunks, >= 1
    const int tid = threadIdx.x;
    const int j = tid;                           // output column for tid < 64
    const size_t mat = (size_t)S * S;

    if (tid < S) wbuf[tid] = 1.0f;
    // load tile 0
    {
        const uint4* src = (const uint4*)(g_buf1 + (size_t)b * mat);
        uint4* dst = (uint4*)Mt[0];
        dst[tid] = src[tid];
        dst[tid + 256] = src[tid + 256];
    }
    __syncthreads();

    float A = 0.f;                               // meaningful in tid 0
    for (int k = 0; k < n; ++k) {
        // prefetch tile k+1 (issue LDG early)
        if (k + 1 < n) {
            const uint4* src = (const uint4*)(g_buf1 + ((size_t)(k + 1) * BB + b) * mat);
            uint4* dst = (uint4*)Mt[(k + 1) & 1];
            dst[tid] = src[tid];
            dst[tid + 256] = src[tid + 256];
        }
        float o = 0.f;
        if (tid < S) {
            const __nv_bfloat16* Mc = Mt[k & 1];
            float a0 = 0.f, a1 = 0.f, a2 = 0.f, a3 = 0.f;
#pragma unroll
            for (int i = 0; i < S; i += 4) {
                a0 = fmaf(wbuf[i + 0], __bfloat162float(Mc[(i + 0) * S + j]), a0);
                a1 = fmaf(wbuf[i + 1], __bfloat162float(Mc[(i + 1) * S + j]), a1);
                a2 = fmaf(wbuf[i + 2], __bfloat162float(Mc[(i + 2) * S + j]), a2);
                a3 = fmaf(wbuf[i + 3], __bfloat162float(Mc[(i + 3) * S + j]), a3);
            }
            o = (a0 + a1) + (a2 + a3);
            float m = o;
#pragma unroll
            for (int of = 16; of; of >>= 1)
                m = fmaxf(m, __shfl_xor_sync(0xffffffffu, m, of));
            if ((tid & 31) == 0) red[tid >> 5] = m;
        }
        __syncthreads();                         // reads of wbuf & Mt[k&1] done
        if (tid == 0) {
            float mm = fmaxf(red[0], red[1]);
            int s = (int)((__float_as_uint(mm) >> 23) & 0xFF) - 126;
            red[2] = __uint_as_float((uint32_t)(127 - s) << 23);   // exact 2^-s
            A += g_off1[k * BB + b] + (float)s;
        }
        __syncthreads();
        if (tid < S) wbuf[j] = o * red[2];
        __syncthreads();                         // wbuf + next tile ready
    }

    if (tid == 0) {
        float ssum = 0.f;
#pragma unroll
        for (int q = 0; q < S; ++q) ssum += wbuf[q];
        out[b] = (float)(((double)log2f(ssum) + (double)A) * 0.6931471805599453094);
    }
}

extern "C" void kernel_launch(void* const* d_in, const int* in_sizes, int n_in,
                              void* d_out, int out_size)
{
    const float* theta   = (const float*)d_in[0];
    const int*   lengths = (const int*)d_in[1];
    float*       out     = (float*)d_out;

    passA<<<dim3(NC, BB), 512>>>(theta, lengths);
    passV<<<BB, 256>>>(lengths, out);
}